// round 12
// baseline (speedup 1.0000x reference)
#include <cuda_runtime.h>
#include <cuda_bf16.h>
#include <cstdint>

#define B_ 1024
#define N_ 8192
#define K_ 4096

__global__ __launch_bounds__(256)
void polar_kernel(const float* __restrict__ info_bits,
                  const int*   __restrict__ u_random,
                  const int*   __restrict__ info_set,
                  float*       __restrict__ out)
{
    // Per-CTA O(1) map: j -> info index (short), -1 if frozen. 16 KB.
    __shared__ short s_map[N_];
    // Packed final codeword (x CTAs only): word (w*32 + L) holds elements
    // i = w*1024 + (L>>2)*128 + bit*4 + (L&3), bit = 0..31.
    __shared__ unsigned SW[256];

    const int bid = blockIdx.x;
    const int t = threadIdx.x;
    const int w = t >> 5;       // warp id (0..7)
    const int l = t & 31;       // lane

    // ---- Build map: init to -1 (int4), then scatter info_set ----
    {
        int4* mi = (int4*)s_map;
        const int4 neg1 = make_int4(-1, -1, -1, -1);
        #pragma unroll
        for (int i = t; i < N_ / 8; i += 256) mi[i] = neg1;
        __syncthreads();
        const int4* is4 = (const int4*)info_set;
        #pragma unroll
        for (int i = t; i < K_ / 4; i += 256) {
            const int4 v = is4[i];          // L2-resident after first wave
            const int k = i * 4;
            s_map[v.x] = (short)k;
            s_map[v.y] = (short)(k + 1);
            s_map[v.z] = (short)(k + 2);
            s_map[v.w] = (short)(k + 3);
        }
    }
    __syncthreads();

    float* out_x = out;
    float* out_f = out + (size_t)1 * B_ * N_;
    float* out_u = out + (size_t)2 * B_ * N_;
    float* out_p = out + (size_t)3 * B_ * N_;   // (B,N,2)
    float* out_r = out + (size_t)5 * B_ * N_;   // (B,N,2)

    if (bid < B_) {
        // ================= fupr CTA: heavy elementwise job =================
        const int b = bid;
        const int4*  ur4 = (const int4*)(u_random + (size_t)b * N_);
        const float* ib  = info_bits + (size_t)b * K_;
        const size_t rb  = (size_t)b * N_;

        #pragma unroll
        for (int m = 0; m < 8; m++) {
            const int j0 = w * 1024 + m * 128 + l * 4;
            const int4 ur = ur4[j0 >> 2];
            const short4 mp = ((const short4*)s_map)[j0 >> 2];  // conflict-free LDS.64

            int u0 = (mp.x >= 0) ? (int)ib[mp.x] : ur.x;
            int u1 = (mp.y >= 0) ? (int)ib[mp.y] : ur.y;
            int u2 = (mp.z >= 0) ? (int)ib[mp.z] : ur.z;
            int u3 = (mp.w >= 0) ? (int)ib[mp.w] : ur.w;
            int f0 = (mp.x >= 0) ? 2 : ur.x;
            int f1 = (mp.y >= 0) ? 2 : ur.y;
            int f2 = (mp.z >= 0) ? 2 : ur.z;
            int f3 = (mp.w >= 0) ? 2 : ur.w;

            const size_t o = rb + (size_t)j0;
            *(float4*)(out_f + o) = make_float4((float)f0, (float)f1, (float)f2, (float)f3);
            *(float4*)(out_u + o) = make_float4((float)u0, (float)u1, (float)u2, (float)u3);

            float4* pp = (float4*)(out_p + 2 * o);
            pp[0] = make_float4(0.5f, 0.5f, 0.5f, 0.5f);
            pp[1] = make_float4(0.5f, 0.5f, 0.5f, 0.5f);

            float4* rr = (float4*)(out_r + 2 * o);
            rr[0] = make_float4(1.0f - (float)ur.x, (float)ur.x,
                                1.0f - (float)ur.y, (float)ur.y);
            rr[1] = make_float4(1.0f - (float)ur.z, (float)ur.z,
                                1.0f - (float)ur.w, (float)ur.w);
        }
    } else {
        // ================= x CTA: light butterfly job (tail filler) ========
        const int b = bid - B_;
        const int4*  ur4 = (const int4*)(u_random + (size_t)b * N_);
        const float* ib  = info_bits + (size_t)b * K_;
        const size_t rb  = (size_t)b * N_;

        unsigned myword = 0;

        #pragma unroll
        for (int m = 0; m < 8; m++) {
            const int j0 = w * 1024 + m * 128 + l * 4;
            const int4 ur = ur4[j0 >> 2];                       // L2 hit (fupr read it)
            const short4 mp = ((const short4*)s_map)[j0 >> 2];

            int u0 = (mp.x >= 0) ? (int)ib[mp.x] : ur.x;
            int u1 = (mp.y >= 0) ? (int)ib[mp.y] : ur.y;
            int u2 = (mp.z >= 0) ? (int)ib[mp.z] : ur.z;
            int u3 = (mp.w >= 0) ? (int)ib[mp.w] : ur.w;

            // Pack: ballot bit 'lane' of ballot_e = u bit of element (m*128 + lane*4 + e)
            unsigned b0 = __ballot_sync(0xFFFFFFFFu, u0);
            unsigned b1 = __ballot_sync(0xFFFFFFFFu, u1);
            unsigned b2 = __ballot_sync(0xFFFFFFFFu, u2);
            unsigned b3 = __ballot_sync(0xFFFFFFFFu, u3);
            if ((l >> 2) == m) {
                const int e = l & 3;
                myword = (e == 0) ? b0 : (e == 1) ? b1 : (e == 2) ? b2 : b3;
            }
        }

        // ---- Butterfly (stages commute). Element index bits in this packing:
        //   bits 0..1 -> L&3, bits 2..6 -> bit-in-word, bits 7..9 -> L>>2,
        //   bits 10..12 -> warp id
        unsigned o1;
        o1 = __shfl_xor_sync(0xFFFFFFFFu, myword, 1);  if (!(l & 1))  myword ^= o1;  // d=1
        o1 = __shfl_xor_sync(0xFFFFFFFFu, myword, 2);  if (!(l & 2))  myword ^= o1;  // d=2
        myword ^= (myword >> 1)  & 0x55555555u;                                      // d=4
        myword ^= (myword >> 2)  & 0x33333333u;                                      // d=8
        myword ^= (myword >> 4)  & 0x0F0F0F0Fu;                                      // d=16
        myword ^= (myword >> 8)  & 0x00FF00FFu;                                      // d=32
        myword ^= (myword >> 16) & 0x0000FFFFu;                                      // d=64
        o1 = __shfl_xor_sync(0xFFFFFFFFu, myword, 4);  if (!(l & 4))  myword ^= o1;  // d=128
        o1 = __shfl_xor_sync(0xFFFFFFFFu, myword, 8);  if (!(l & 8))  myword ^= o1;  // d=256
        o1 = __shfl_xor_sync(0xFFFFFFFFu, myword, 16); if (!(l & 16)) myword ^= o1;  // d=512

        SW[t] = myword;
        __syncthreads();
        if (!(w & 1)) SW[t] ^= SW[t + 32];   // d=1024
        __syncthreads();
        if (!(w & 2)) SW[t] ^= SW[t + 64];   // d=2048
        __syncthreads();
        if (!(w & 4)) SW[t] ^= SW[t + 128];  // d=4096
        __syncthreads();

        // ---- x[j] = packed_bit[brev13(j)], coalesced float4 stores ----
        #pragma unroll
        for (int m = 0; m < 8; m++) {
            const int j0 = m * 1024 + t * 4;                 // j0 multiple of 4
            const unsigned i0 = __brev((unsigned)j0) >> 19;  // bits 11,12 are 0
            const unsigned idx0 = ((i0 >> 10) << 5) | (((i0 >> 7) & 7) << 2) | (i0 & 3);
            const unsigned bit  = (i0 >> 2) & 31;
            // j bit0 -> i bit12 -> +128 words; j bit1 -> i bit11 -> +64 words
            const float x0 = (float)((SW[idx0]       >> bit) & 1u);
            const float x1 = (float)((SW[idx0 + 128] >> bit) & 1u);
            const float x2 = (float)((SW[idx0 + 64]  >> bit) & 1u);
            const float x3 = (float)((SW[idx0 + 192] >> bit) & 1u);
            *(float4*)(out_x + rb + (size_t)j0) = make_float4(x0, x1, x2, x3);
        }
    }
}

extern "C" void kernel_launch(void* const* d_in, const int* in_sizes, int n_in,
                              void* d_out, int out_size) {
    const float* info_bits = (const float*)d_in[0];
    const int*   u_random  = (const int*)d_in[1];
    const int*   info_set  = (const int*)d_in[2];
    float* out = (float*)d_out;

    polar_kernel<<<2 * B_, 256>>>(info_bits, u_random, info_set, out);
}

// round 13
// speedup vs baseline: 1.0763x; 1.0763x over previous
#include <cuda_runtime.h>
#include <cuda_bf16.h>
#include <cstdint>

#define B_ 1024
#define N_ 8192
#define K_ 4096
#define T_ 128   // threads per CTA; each thread owns TWO packed words

__global__ __launch_bounds__(T_)
void polar_kernel(const float* __restrict__ info_bits,
                  const int*   __restrict__ u_random,
                  const int*   __restrict__ info_set,
                  float*       __restrict__ out)
{
    // Per-CTA O(1) map: j -> info index (short), -1 if frozen. 16 KB.
    __shared__ short s_map[N_];
    // Packed codeword, 256 words: word W = w*32+L holds elements
    // i = w*1024 + (L>>2)*128 + bit*4 + (L&3), bit = 0..31.  (w = 0..7)
    __shared__ unsigned SW[256];

    const int b = blockIdx.x;
    const int t = threadIdx.x;      // 0..127
    const int wp = t >> 5;          // physical warp 0..3
    const int l = t & 31;           // lane

    // ---- Build map: init to -1 (int4), then scatter info_set ----
    {
        int4* mi = (int4*)s_map;
        const int4 neg1 = make_int4(-1, -1, -1, -1);
        #pragma unroll
        for (int i = t; i < N_ / 8; i += T_) mi[i] = neg1;
        __syncthreads();
        const int4* is4 = (const int4*)info_set;
        #pragma unroll
        for (int i = t; i < K_ / 4; i += T_) {
            const int4 v = is4[i];          // L2-resident after first wave
            const int k = i * 4;
            s_map[v.x] = (short)k;
            s_map[v.y] = (short)(k + 1);
            s_map[v.z] = (short)(k + 2);
            s_map[v.w] = (short)(k + 3);
        }
    }
    __syncthreads();

    const int4*  ur4 = (const int4*)(u_random + (size_t)b * N_);
    const float* ib  = info_bits + (size_t)b * K_;

    float* out_x = out;
    float* out_f = out + (size_t)1 * B_ * N_;
    float* out_u = out + (size_t)2 * B_ * N_;
    float* out_p = out + (size_t)3 * B_ * N_;   // (B,N,2)
    float* out_r = out + (size_t)5 * B_ * N_;   // (B,N,2)
    const size_t rb = (size_t)b * N_;

    // Thread owns virtual warps w = wp (word t) and w = wp+4 (word t+128).
    unsigned myword0 = 0, myword1 = 0;

    // ---- Pass 1 (two half-passes, one per virtual warp): coalesced load,
    //      O(1) smem map lookup, emit f/u/p/r, ballot-pack u bits ----
    #pragma unroll
    for (int v = 0; v < 2; v++) {
        const int w = wp + 4 * v;
        #pragma unroll
        for (int m = 0; m < 8; m++) {
            const int j0 = w * 1024 + m * 128 + l * 4;
            const int4 ur = ur4[j0 >> 2];
            const short4 mp = ((const short4*)s_map)[j0 >> 2];  // conflict-free LDS.64

            int u0 = (mp.x >= 0) ? (int)ib[mp.x] : ur.x;
            int u1 = (mp.y >= 0) ? (int)ib[mp.y] : ur.y;
            int u2 = (mp.z >= 0) ? (int)ib[mp.z] : ur.z;
            int u3 = (mp.w >= 0) ? (int)ib[mp.w] : ur.w;
            int f0 = (mp.x >= 0) ? 2 : ur.x;
            int f1 = (mp.y >= 0) ? 2 : ur.y;
            int f2 = (mp.z >= 0) ? 2 : ur.z;
            int f3 = (mp.w >= 0) ? 2 : ur.w;

            const size_t o = rb + (size_t)j0;
            *(float4*)(out_f + o) = make_float4((float)f0, (float)f1, (float)f2, (float)f3);
            *(float4*)(out_u + o) = make_float4((float)u0, (float)u1, (float)u2, (float)u3);

            float4* pp = (float4*)(out_p + 2 * o);
            pp[0] = make_float4(0.5f, 0.5f, 0.5f, 0.5f);
            pp[1] = make_float4(0.5f, 0.5f, 0.5f, 0.5f);

            float4* rr = (float4*)(out_r + 2 * o);
            rr[0] = make_float4(1.0f - (float)ur.x, (float)ur.x,
                                1.0f - (float)ur.y, (float)ur.y);
            rr[1] = make_float4(1.0f - (float)ur.z, (float)ur.z,
                                1.0f - (float)ur.w, (float)ur.w);

            // ballot bit 'lane' of ballot_e = u bit of element (w*1024 + m*128 + lane*4 + e)
            unsigned b0 = __ballot_sync(0xFFFFFFFFu, u0);
            unsigned b1 = __ballot_sync(0xFFFFFFFFu, u1);
            unsigned b2 = __ballot_sync(0xFFFFFFFFu, u2);
            unsigned b3 = __ballot_sync(0xFFFFFFFFu, u3);
            if ((l >> 2) == m) {
                const int e = l & 3;
                const unsigned sel = (e == 0) ? b0 : (e == 1) ? b1 : (e == 2) ? b2 : b3;
                if (v == 0) myword0 = sel; else myword1 = sel;
            }
        }
    }

    // ---- Butterfly (stages commute). Element index bits:
    //   0..1 -> W&3, 2..6 -> bit-in-word, 7..9 -> (W>>2)&7, 10..12 -> W>>5 (=w)
    // Intra-word + intra-physical-warp stages, applied to both words:
    unsigned o1;
    o1 = __shfl_xor_sync(0xFFFFFFFFu, myword0, 1);  if (!(l & 1))  myword0 ^= o1;  // d=1
    o1 = __shfl_xor_sync(0xFFFFFFFFu, myword1, 1);  if (!(l & 1))  myword1 ^= o1;
    o1 = __shfl_xor_sync(0xFFFFFFFFu, myword0, 2);  if (!(l & 2))  myword0 ^= o1;  // d=2
    o1 = __shfl_xor_sync(0xFFFFFFFFu, myword1, 2);  if (!(l & 2))  myword1 ^= o1;
    myword0 ^= (myword0 >> 1)  & 0x55555555u;  myword1 ^= (myword1 >> 1)  & 0x55555555u; // d=4
    myword0 ^= (myword0 >> 2)  & 0x33333333u;  myword1 ^= (myword1 >> 2)  & 0x33333333u; // d=8
    myword0 ^= (myword0 >> 4)  & 0x0F0F0F0Fu;  myword1 ^= (myword1 >> 4)  & 0x0F0F0F0Fu; // d=16
    myword0 ^= (myword0 >> 8)  & 0x00FF00FFu;  myword1 ^= (myword1 >> 8)  & 0x00FF00FFu; // d=32
    myword0 ^= (myword0 >> 16) & 0x0000FFFFu;  myword1 ^= (myword1 >> 16) & 0x0000FFFFu; // d=64
    o1 = __shfl_xor_sync(0xFFFFFFFFu, myword0, 4);  if (!(l & 4))  myword0 ^= o1;  // d=128
    o1 = __shfl_xor_sync(0xFFFFFFFFu, myword1, 4);  if (!(l & 4))  myword1 ^= o1;
    o1 = __shfl_xor_sync(0xFFFFFFFFu, myword0, 8);  if (!(l & 8))  myword0 ^= o1;  // d=256
    o1 = __shfl_xor_sync(0xFFFFFFFFu, myword1, 8);  if (!(l & 8))  myword1 ^= o1;
    o1 = __shfl_xor_sync(0xFFFFFFFFu, myword0, 16); if (!(l & 16)) myword0 ^= o1;  // d=512
    o1 = __shfl_xor_sync(0xFFFFFFFFu, myword1, 16); if (!(l & 16)) myword1 ^= o1;

    // d=4096 (element bit 12 = w bit 2): pairs the two words of THIS thread.
    myword0 ^= myword1;

    SW[t]       = myword0;   // word W = wp*32 + l       (w = wp)
    SW[t + 128] = myword1;   // word W = (wp+4)*32 + l   (w = wp+4)
    __syncthreads();
    // d=1024 (w bit 0), d=2048 (w bit 1): cross physical warps, both halves.
    if (!(wp & 1)) { SW[t] ^= SW[t + 32];  SW[t + 128] ^= SW[t + 160]; }
    __syncthreads();
    if (!(wp & 2)) { SW[t] ^= SW[t + 64];  SW[t + 128] ^= SW[t + 192]; }
    __syncthreads();

    // ---- Pass 3: x[j] = packed_bit[brev13(j)], coalesced float4 stores ----
    #pragma unroll
    for (int m = 0; m < 16; m++) {
        const int j0 = m * 512 + t * 4;                  // j0 multiple of 4
        const unsigned i0 = __brev((unsigned)j0) >> 19;  // bits 11,12 are 0
        const unsigned idx0 = ((i0 >> 10) << 5) | (((i0 >> 7) & 7) << 2) | (i0 & 3);
        const unsigned bit  = (i0 >> 2) & 31;
        // j bit0 -> i bit12 -> +128 words; j bit1 -> i bit11 -> +64 words
        const float x0 = (float)((SW[idx0]       >> bit) & 1u);
        const float x1 = (float)((SW[idx0 + 128] >> bit) & 1u);
        const float x2 = (float)((SW[idx0 + 64]  >> bit) & 1u);
        const float x3 = (float)((SW[idx0 + 192] >> bit) & 1u);
        *(float4*)(out_x + rb + (size_t)j0) = make_float4(x0, x1, x2, x3);
    }
}

extern "C" void kernel_launch(void* const* d_in, const int* in_sizes, int n_in,
                              void* d_out, int out_size) {
    const float* info_bits = (const float*)d_in[0];
    const int*   u_random  = (const int*)d_in[1];
    const int*   info_set  = (const int*)d_in[2];
    float* out = (float*)d_out;

    polar_kernel<<<B_, T_>>>(info_bits, u_random, info_set, out);
}

// round 15
// speedup vs baseline: 1.1646x; 1.0820x over previous
#include <cuda_runtime.h>
#include <cuda_bf16.h>
#include <cstdint>

#define B_ 1024
#define N_ 8192
#define K_ 4096

__global__ __launch_bounds__(256)
void polar_kernel(const float* __restrict__ info_bits,
                  const int*   __restrict__ u_random,
                  const int*   __restrict__ info_set,
                  float*       __restrict__ out)
{
    // Per-CTA O(1) map: j -> info index (short), -1 if frozen. 16 KB.
    __shared__ short s_map[N_];
    // Packed final codeword: word (w*32 + L) holds elements
    // i = w*1024 + (L>>2)*128 + bit*4 + (L&3), bit = 0..31.
    __shared__ unsigned SW[256];

    const int b = blockIdx.x;
    const int t = threadIdx.x;
    const int w = t >> 5;       // warp id (0..7)
    const int l = t & 31;       // lane

    // ---- Build map: init to -1 (int4), then scatter info_set ----
    {
        int4* mi = (int4*)s_map;
        const int4 neg1 = make_int4(-1, -1, -1, -1);
        #pragma unroll
        for (int i = t; i < N_ / 8; i += 256) mi[i] = neg1;
        __syncthreads();
        const int4* is4 = (const int4*)info_set;
        #pragma unroll
        for (int i = t; i < K_ / 4; i += 256) {
            const int4 v = is4[i];          // L2-resident after first wave
            const int k = i * 4;
            s_map[v.x] = (short)k;
            s_map[v.y] = (short)(k + 1);
            s_map[v.z] = (short)(k + 2);
            s_map[v.w] = (short)(k + 3);
        }
    }
    __syncthreads();

    const int4*  ur4 = (const int4*)(u_random + (size_t)b * N_);
    const float* ib  = info_bits + (size_t)b * K_;

    float* out_x = out;
    float* out_f = out + (size_t)1 * B_ * N_;
    float* out_u = out + (size_t)2 * B_ * N_;
    float* out_p = out + (size_t)3 * B_ * N_;   // (B,N,2)
    float* out_r = out + (size_t)5 * B_ * N_;   // (B,N,2)
    const size_t rb = (size_t)b * N_;

    unsigned myword = 0;

    // ---- Pass 1: coalesced load, O(1) smem map lookup (one short4 LDS),
    //      emit f/u/p/r, ballot-pack u bits ----
    #pragma unroll
    for (int m = 0; m < 8; m++) {
        const int j0 = w * 1024 + m * 128 + l * 4;
        const int4 ur = ur4[j0 >> 2];
        const short4 mp = ((const short4*)s_map)[j0 >> 2];   // conflict-free LDS.64

        int u0 = (mp.x >= 0) ? (int)ib[mp.x] : ur.x;
        int u1 = (mp.y >= 0) ? (int)ib[mp.y] : ur.y;
        int u2 = (mp.z >= 0) ? (int)ib[mp.z] : ur.z;
        int u3 = (mp.w >= 0) ? (int)ib[mp.w] : ur.w;
        int f0 = (mp.x >= 0) ? 2 : ur.x;
        int f1 = (mp.y >= 0) ? 2 : ur.y;
        int f2 = (mp.z >= 0) ? 2 : ur.z;
        int f3 = (mp.w >= 0) ? 2 : ur.w;

        const size_t o = rb + (size_t)j0;
        *(float4*)(out_f + o) = make_float4((float)f0, (float)f1, (float)f2, (float)f3);
        *(float4*)(out_u + o) = make_float4((float)u0, (float)u1, (float)u2, (float)u3);

        float4* pp = (float4*)(out_p + 2 * o);
        pp[0] = make_float4(0.5f, 0.5f, 0.5f, 0.5f);
        pp[1] = make_float4(0.5f, 0.5f, 0.5f, 0.5f);

        float4* rr = (float4*)(out_r + 2 * o);
        rr[0] = make_float4(1.0f - (float)ur.x, (float)ur.x,
                            1.0f - (float)ur.y, (float)ur.y);
        rr[1] = make_float4(1.0f - (float)ur.z, (float)ur.z,
                            1.0f - (float)ur.w, (float)ur.w);

        // Pack: ballot bit 'lane' of ballot_e = u bit of element (m*128 + lane*4 + e)
        unsigned b0 = __ballot_sync(0xFFFFFFFFu, u0);
        unsigned b1 = __ballot_sync(0xFFFFFFFFu, u1);
        unsigned b2 = __ballot_sync(0xFFFFFFFFu, u2);
        unsigned b3 = __ballot_sync(0xFFFFFFFFu, u3);
        if ((l >> 2) == m) {
            const int e = l & 3;
            myword = (e == 0) ? b0 : (e == 1) ? b1 : (e == 2) ? b2 : b3;
        }
    }

    // ---- Butterfly (stages commute). Element index bits in this packing:
    //   bits 0..1  -> L&3, bits 2..6 -> bit-in-word, bits 7..9 -> L>>2,
    //   bits 10..12 -> warp id
    unsigned o1;
    o1 = __shfl_xor_sync(0xFFFFFFFFu, myword, 1);  if (!(l & 1))  myword ^= o1;  // d=1
    o1 = __shfl_xor_sync(0xFFFFFFFFu, myword, 2);  if (!(l & 2))  myword ^= o1;  // d=2
    myword ^= (myword >> 1)  & 0x55555555u;                                      // d=4
    myword ^= (myword >> 2)  & 0x33333333u;                                      // d=8
    myword ^= (myword >> 4)  & 0x0F0F0F0Fu;                                      // d=16
    myword ^= (myword >> 8)  & 0x00FF00FFu;                                      // d=32
    myword ^= (myword >> 16) & 0x0000FFFFu;                                      // d=64
    o1 = __shfl_xor_sync(0xFFFFFFFFu, myword, 4);  if (!(l & 4))  myword ^= o1;  // d=128
    o1 = __shfl_xor_sync(0xFFFFFFFFu, myword, 8);  if (!(l & 8))  myword ^= o1;  // d=256
    o1 = __shfl_xor_sync(0xFFFFFFFFu, myword, 16); if (!(l & 16)) myword ^= o1;  // d=512

    SW[t] = myword;
    __syncthreads();
    if (!(w & 1)) SW[t] ^= SW[t + 32];   // d=1024
    __syncthreads();
    if (!(w & 2)) SW[t] ^= SW[t + 64];   // d=2048
    __syncthreads();
    if (!(w & 4)) SW[t] ^= SW[t + 128];  // d=4096
    __syncthreads();

    // ---- Pass 3: x[j] = packed_bit[brev13(j)], coalesced float4 stores ----
    #pragma unroll
    for (int m = 0; m < 8; m++) {
        const int j0 = m * 1024 + t * 4;                 // j0 multiple of 4
        const unsigned i0 = __brev((unsigned)j0) >> 19;  // bits 11,12 are 0
        const unsigned idx0 = ((i0 >> 10) << 5) | (((i0 >> 7) & 7) << 2) | (i0 & 3);
        const unsigned bit  = (i0 >> 2) & 31;
        // j bit0 -> i bit12 -> +128 words; j bit1 -> i bit11 -> +64 words
        const float x0 = (float)((SW[idx0]       >> bit) & 1u);
        const float x1 = (float)((SW[idx0 + 128] >> bit) & 1u);
        const float x2 = (float)((SW[idx0 + 64]  >> bit) & 1u);
        const float x3 = (float)((SW[idx0 + 192] >> bit) & 1u);
        *(float4*)(out_x + rb + (size_t)j0) = make_float4(x0, x1, x2, x3);
    }
}

extern "C" void kernel_launch(void* const* d_in, const int* in_sizes, int n_in,
                              void* d_out, int out_size) {
    const float* info_bits = (const float*)d_in[0];
    const int*   u_random  = (const int*)d_in[1];
    const int*   info_set  = (const int*)d_in[2];
    float* out = (float*)d_out;

    polar_kernel<<<B_, 256>>>(info_bits, u_random, info_set, out);
}

// round 16
// speedup vs baseline: 1.2191x; 1.0468x over previous
#include <cuda_runtime.h>
#include <cuda_bf16.h>
#include <cstdint>

#define B_ 1024
#define N_ 8192
#define K_ 4096

__global__ __launch_bounds__(256)
void polar_kernel(const float* __restrict__ info_bits,
                  const int*   __restrict__ u_random,
                  const int*   __restrict__ info_set,
                  float*       __restrict__ out)
{
    // Per-CTA O(1) map: j -> info index (short), -1 if frozen. 16 KB.
    __shared__ short s_map[N_];
    // Coalesced-staged info_bits row (gathered from smem, not global). 16 KB.
    __shared__ float s_ib[K_];
    // Packed final codeword: word (w*32 + L) holds elements
    // i = w*1024 + (L>>2)*128 + bit*4 + (L&3), bit = 0..31.
    __shared__ unsigned SW[256];

    const int b = blockIdx.x;
    const int t = threadIdx.x;
    const int w = t >> 5;       // warp id (0..7)
    const int l = t & 31;       // lane

    // ---- Stage ib row (coalesced float4) + build map ----
    {
        const float4* ib4 = (const float4*)(info_bits + (size_t)b * K_);
        float4* sib4 = (float4*)s_ib;
        #pragma unroll
        for (int i = t; i < K_ / 4; i += 256) sib4[i] = ib4[i];

        int4* mi = (int4*)s_map;
        const int4 neg1 = make_int4(-1, -1, -1, -1);
        #pragma unroll
        for (int i = t; i < N_ / 8; i += 256) mi[i] = neg1;
        __syncthreads();
        const int4* is4 = (const int4*)info_set;
        #pragma unroll
        for (int i = t; i < K_ / 4; i += 256) {
            const int4 v = is4[i];          // L2-resident after first wave
            const int k = i * 4;
            s_map[v.x] = (short)k;
            s_map[v.y] = (short)(k + 1);
            s_map[v.z] = (short)(k + 2);
            s_map[v.w] = (short)(k + 3);
        }
    }
    __syncthreads();

    const int4* ur4 = (const int4*)(u_random + (size_t)b * N_);

    float* out_x = out;
    float* out_f = out + (size_t)1 * B_ * N_;
    float* out_u = out + (size_t)2 * B_ * N_;
    float* out_p = out + (size_t)3 * B_ * N_;   // (B,N,2)
    float* out_r = out + (size_t)5 * B_ * N_;   // (B,N,2)
    const size_t rb = (size_t)b * N_;

    unsigned myword = 0;

    // ---- Pass 1: coalesced load, O(1) smem map lookup (one short4 LDS),
    //      smem ib gather, emit f/u/p/r, ballot-pack u bits ----
    #pragma unroll
    for (int m = 0; m < 8; m++) {
        const int j0 = w * 1024 + m * 128 + l * 4;
        const int4 ur = ur4[j0 >> 2];
        const short4 mp = ((const short4*)s_map)[j0 >> 2];   // conflict-free LDS.64

        int u0 = (mp.x >= 0) ? (int)s_ib[mp.x] : ur.x;
        int u1 = (mp.y >= 0) ? (int)s_ib[mp.y] : ur.y;
        int u2 = (mp.z >= 0) ? (int)s_ib[mp.z] : ur.z;
        int u3 = (mp.w >= 0) ? (int)s_ib[mp.w] : ur.w;
        int f0 = (mp.x >= 0) ? 2 : ur.x;
        int f1 = (mp.y >= 0) ? 2 : ur.y;
        int f2 = (mp.z >= 0) ? 2 : ur.z;
        int f3 = (mp.w >= 0) ? 2 : ur.w;

        const size_t o = rb + (size_t)j0;
        *(float4*)(out_f + o) = make_float4((float)f0, (float)f1, (float)f2, (float)f3);
        *(float4*)(out_u + o) = make_float4((float)u0, (float)u1, (float)u2, (float)u3);

        float4* pp = (float4*)(out_p + 2 * o);
        pp[0] = make_float4(0.5f, 0.5f, 0.5f, 0.5f);
        pp[1] = make_float4(0.5f, 0.5f, 0.5f, 0.5f);

        float4* rr = (float4*)(out_r + 2 * o);
        rr[0] = make_float4(1.0f - (float)ur.x, (float)ur.x,
                            1.0f - (float)ur.y, (float)ur.y);
        rr[1] = make_float4(1.0f - (float)ur.z, (float)ur.z,
                            1.0f - (float)ur.w, (float)ur.w);

        // Pack: ballot bit 'lane' of ballot_e = u bit of element (m*128 + lane*4 + e)
        unsigned b0 = __ballot_sync(0xFFFFFFFFu, u0);
        unsigned b1 = __ballot_sync(0xFFFFFFFFu, u1);
        unsigned b2 = __ballot_sync(0xFFFFFFFFu, u2);
        unsigned b3 = __ballot_sync(0xFFFFFFFFu, u3);
        if ((l >> 2) == m) {
            const int e = l & 3;
            myword = (e == 0) ? b0 : (e == 1) ? b1 : (e == 2) ? b2 : b3;
        }
    }

    // ---- Butterfly (stages commute). Element index bits in this packing:
    //   bits 0..1  -> L&3, bits 2..6 -> bit-in-word, bits 7..9 -> L>>2,
    //   bits 10..12 -> warp id
    unsigned o1;
    o1 = __shfl_xor_sync(0xFFFFFFFFu, myword, 1);  if (!(l & 1))  myword ^= o1;  // d=1
    o1 = __shfl_xor_sync(0xFFFFFFFFu, myword, 2);  if (!(l & 2))  myword ^= o1;  // d=2
    myword ^= (myword >> 1)  & 0x55555555u;                                      // d=4
    myword ^= (myword >> 2)  & 0x33333333u;                                      // d=8
    myword ^= (myword >> 4)  & 0x0F0F0F0Fu;                                      // d=16
    myword ^= (myword >> 8)  & 0x00FF00FFu;                                      // d=32
    myword ^= (myword >> 16) & 0x0000FFFFu;                                      // d=64
    o1 = __shfl_xor_sync(0xFFFFFFFFu, myword, 4);  if (!(l & 4))  myword ^= o1;  // d=128
    o1 = __shfl_xor_sync(0xFFFFFFFFu, myword, 8);  if (!(l & 8))  myword ^= o1;  // d=256
    o1 = __shfl_xor_sync(0xFFFFFFFFu, myword, 16); if (!(l & 16)) myword ^= o1;  // d=512

    SW[t] = myword;
    __syncthreads();
    if (!(w & 1)) SW[t] ^= SW[t + 32];   // d=1024
    __syncthreads();
    if (!(w & 2)) SW[t] ^= SW[t + 64];   // d=2048
    __syncthreads();
    if (!(w & 4)) SW[t] ^= SW[t + 128];  // d=4096
    __syncthreads();

    // ---- Pass 3: x[j] = packed_bit[brev13(j)], coalesced float4 stores ----
    #pragma unroll
    for (int m = 0; m < 8; m++) {
        const int j0 = m * 1024 + t * 4;                 // j0 multiple of 4
        const unsigned i0 = __brev((unsigned)j0) >> 19;  // bits 11,12 are 0
        const unsigned idx0 = ((i0 >> 10) << 5) | (((i0 >> 7) & 7) << 2) | (i0 & 3);
        const unsigned bit  = (i0 >> 2) & 31;
        // j bit0 -> i bit12 -> +128 words; j bit1 -> i bit11 -> +64 words
        const float x0 = (float)((SW[idx0]       >> bit) & 1u);
        const float x1 = (float)((SW[idx0 + 128] >> bit) & 1u);
        const float x2 = (float)((SW[idx0 + 64]  >> bit) & 1u);
        const float x3 = (float)((SW[idx0 + 192] >> bit) & 1u);
        *(float4*)(out_x + rb + (size_t)j0) = make_float4(x0, x1, x2, x3);
    }
}

extern "C" void kernel_launch(void* const* d_in, const int* in_sizes, int n_in,
                              void* d_out, int out_size) {
    const float* info_bits = (const float*)d_in[0];
    const int*   u_random  = (const int*)d_in[1];
    const int*   info_set  = (const int*)d_in[2];
    float* out = (float*)d_out;

    polar_kernel<<<B_, 256>>>(info_bits, u_random, info_set, out);
}

// round 17
// speedup vs baseline: 1.2198x; 1.0006x over previous
#include <cuda_runtime.h>
#include <cuda_bf16.h>
#include <cstdint>

#define B_ 1024
#define N_ 8192
#define K_ 4096

__global__ __launch_bounds__(256)
void polar_kernel(const float* __restrict__ info_bits,
                  const int*   __restrict__ u_random,
                  const int*   __restrict__ info_set,
                  float*       __restrict__ out)
{
    // Per-CTA fused map: s_map[j] = -1 if frozen, else the info BIT VALUE
    // (0/1) for this row. The ib row is read once, coalesced, at build time
    // — no gathers anywhere in the kernel. 16 KB.
    __shared__ short s_map[N_];
    // Packed final codeword: word (w*32 + L) holds elements
    // i = w*1024 + (L>>2)*128 + bit*4 + (L&3), bit = 0..31.
    __shared__ unsigned SW[256];

    const int b = blockIdx.x;
    const int t = threadIdx.x;
    const int w = t >> 5;       // warp id (0..7)
    const int l = t & 31;       // lane

    // ---- Build fused map: init to -1 (int4), scatter ib values ----
    {
        int4* mi = (int4*)s_map;
        const int4 neg1 = make_int4(-1, -1, -1, -1);
        #pragma unroll
        for (int i = t; i < N_ / 8; i += 256) mi[i] = neg1;
        __syncthreads();
        const int4*   is4 = (const int4*)info_set;
        const float4* ib4 = (const float4*)(info_bits + (size_t)b * K_);
        #pragma unroll
        for (int i = t; i < K_ / 4; i += 256) {
            const int4   v  = is4[i];    // L2-resident after first wave
            const float4 bv = ib4[i];    // coalesced — ib read exactly once
            s_map[v.x] = (short)bv.x;    // 0 or 1
            s_map[v.y] = (short)bv.y;
            s_map[v.z] = (short)bv.z;
            s_map[v.w] = (short)bv.w;
        }
    }
    __syncthreads();

    const int4* ur4 = (const int4*)(u_random + (size_t)b * N_);

    float* out_x = out;
    float* out_f = out + (size_t)1 * B_ * N_;
    float* out_u = out + (size_t)2 * B_ * N_;
    float* out_p = out + (size_t)3 * B_ * N_;   // (B,N,2)
    float* out_r = out + (size_t)5 * B_ * N_;   // (B,N,2)
    const size_t rb = (size_t)b * N_;

    unsigned myword = 0;

    // ---- Pass 1: coalesced load, one short4 LDS, pure selects,
    //      emit f/u/p/r, ballot-pack u bits ----
    #pragma unroll
    for (int m = 0; m < 8; m++) {
        const int j0 = w * 1024 + m * 128 + l * 4;
        const int4 ur = ur4[j0 >> 2];
        const short4 mp = ((const short4*)s_map)[j0 >> 2];   // conflict-free LDS.64

        const int u0 = (mp.x >= 0) ? mp.x : ur.x;
        const int u1 = (mp.y >= 0) ? mp.y : ur.y;
        const int u2 = (mp.z >= 0) ? mp.z : ur.z;
        const int u3 = (mp.w >= 0) ? mp.w : ur.w;
        const int f0 = (mp.x >= 0) ? 2 : ur.x;
        const int f1 = (mp.y >= 0) ? 2 : ur.y;
        const int f2 = (mp.z >= 0) ? 2 : ur.z;
        const int f3 = (mp.w >= 0) ? 2 : ur.w;

        const size_t o = rb + (size_t)j0;
        *(float4*)(out_f + o) = make_float4((float)f0, (float)f1, (float)f2, (float)f3);
        *(float4*)(out_u + o) = make_float4((float)u0, (float)u1, (float)u2, (float)u3);

        float4* pp = (float4*)(out_p + 2 * o);
        pp[0] = make_float4(0.5f, 0.5f, 0.5f, 0.5f);
        pp[1] = make_float4(0.5f, 0.5f, 0.5f, 0.5f);

        float4* rr = (float4*)(out_r + 2 * o);
        rr[0] = make_float4(1.0f - (float)ur.x, (float)ur.x,
                            1.0f - (float)ur.y, (float)ur.y);
        rr[1] = make_float4(1.0f - (float)ur.z, (float)ur.z,
                            1.0f - (float)ur.w, (float)ur.w);

        // Pack: ballot bit 'lane' of ballot_e = u bit of element (m*128 + lane*4 + e)
        unsigned b0 = __ballot_sync(0xFFFFFFFFu, u0);
        unsigned b1 = __ballot_sync(0xFFFFFFFFu, u1);
        unsigned b2 = __ballot_sync(0xFFFFFFFFu, u2);
        unsigned b3 = __ballot_sync(0xFFFFFFFFu, u3);
        if ((l >> 2) == m) {
            const int e = l & 3;
            myword = (e == 0) ? b0 : (e == 1) ? b1 : (e == 2) ? b2 : b3;
        }
    }

    // ---- Butterfly (stages commute). Element index bits in this packing:
    //   bits 0..1  -> L&3, bits 2..6 -> bit-in-word, bits 7..9 -> L>>2,
    //   bits 10..12 -> warp id
    unsigned o1;
    o1 = __shfl_xor_sync(0xFFFFFFFFu, myword, 1);  if (!(l & 1))  myword ^= o1;  // d=1
    o1 = __shfl_xor_sync(0xFFFFFFFFu, myword, 2);  if (!(l & 2))  myword ^= o1;  // d=2
    myword ^= (myword >> 1)  & 0x55555555u;                                      // d=4
    myword ^= (myword >> 2)  & 0x33333333u;                                      // d=8
    myword ^= (myword >> 4)  & 0x0F0F0F0Fu;                                      // d=16
    myword ^= (myword >> 8)  & 0x00FF00FFu;                                      // d=32
    myword ^= (myword >> 16) & 0x0000FFFFu;                                      // d=64
    o1 = __shfl_xor_sync(0xFFFFFFFFu, myword, 4);  if (!(l & 4))  myword ^= o1;  // d=128
    o1 = __shfl_xor_sync(0xFFFFFFFFu, myword, 8);  if (!(l & 8))  myword ^= o1;  // d=256
    o1 = __shfl_xor_sync(0xFFFFFFFFu, myword, 16); if (!(l & 16)) myword ^= o1;  // d=512

    SW[t] = myword;
    __syncthreads();
    if (!(w & 1)) SW[t] ^= SW[t + 32];   // d=1024
    __syncthreads();
    if (!(w & 2)) SW[t] ^= SW[t + 64];   // d=2048
    __syncthreads();
    if (!(w & 4)) SW[t] ^= SW[t + 128];  // d=4096
    __syncthreads();

    // ---- Pass 3: x[j] = packed_bit[brev13(j)], coalesced float4 stores ----
    #pragma unroll
    for (int m = 0; m < 8; m++) {
        const int j0 = m * 1024 + t * 4;                 // j0 multiple of 4
        const unsigned i0 = __brev((unsigned)j0) >> 19;  // bits 11,12 are 0
        const unsigned idx0 = ((i0 >> 10) << 5) | (((i0 >> 7) & 7) << 2) | (i0 & 3);
        const unsigned bit  = (i0 >> 2) & 31;
        // j bit0 -> i bit12 -> +128 words; j bit1 -> i bit11 -> +64 words
        const float x0 = (float)((SW[idx0]       >> bit) & 1u);
        const float x1 = (float)((SW[idx0 + 128] >> bit) & 1u);
        const float x2 = (float)((SW[idx0 + 64]  >> bit) & 1u);
        const float x3 = (float)((SW[idx0 + 192] >> bit) & 1u);
        *(float4*)(out_x + rb + (size_t)j0) = make_float4(x0, x1, x2, x3);
    }
}

extern "C" void kernel_launch(void* const* d_in, const int* in_sizes, int n_in,
                              void* d_out, int out_size) {
    const float* info_bits = (const float*)d_in[0];
    const int*   u_random  = (const int*)d_in[1];
    const int*   info_set  = (const int*)d_in[2];
    float* out = (float*)d_out;

    polar_kernel<<<B_, 256>>>(info_bits, u_random, info_set, out);
}